// round 16
// baseline (speedup 1.0000x reference)
#include <cuda_runtime.h>
#include <cuda_bf16.h>
#include <cstdint>

#define BSZ 2
#define SEQ 2048
#define DMODEL 1024
#define NHEAD 16
#define DHEAD 64

constexpr int GM = BSZ * SEQ;     // 4096
constexpr int GN = DMODEL;        // 1024
constexpr int GK = DMODEL;        // 1024

// ---------------- scratch (allocation-free device globals) ----------------
__device__ __nv_bfloat16 g_ah[3][GM * GK];
__device__ __nv_bfloat16 g_al[3][GM * GK];
__device__ __nv_bfloat16 g_wh[4][GN * GK];
__device__ __nv_bfloat16 g_wl[4][GN * GK];
__device__ __nv_bfloat16 g_qh[BSZ * NHEAD * SEQ * DHEAD];
__device__ __nv_bfloat16 g_ql[BSZ * NHEAD * SEQ * DHEAD];
__device__ __nv_bfloat16 g_kh2[BSZ * NHEAD * SEQ * DHEAD];
__device__ __nv_bfloat16 g_kl2[BSZ * NHEAD * SEQ * DHEAD];
__device__ __nv_bfloat16 g_vh2[BSZ * NHEAD * SEQ * DHEAD];
__device__ __nv_bfloat16 g_vl2[BSZ * NHEAD * SEQ * DHEAD];
__device__ __nv_bfloat16 g_ch[GM * GK];
__device__ __nv_bfloat16 g_cl[GM * GK];

// ---------------------------- PTX helpers ---------------------------------
__device__ __forceinline__ uint32_t smem_u32(const void* p) {
    uint32_t a;
    asm("{ .reg .u64 t; cvta.to.shared.u64 t, %1; cvt.u32.u64 %0, t; }"
        : "=r"(a) : "l"(p));
    return a;
}
__device__ __forceinline__ void cp16(uint32_t dst, const void* src) {
    asm volatile("cp.async.cg.shared.global [%0], [%1], 16;"
                 :: "r"(dst), "l"(src) : "memory");
}
#define CP_COMMIT() asm volatile("cp.async.commit_group;" ::: "memory")
#define CP_WAIT1()  asm volatile("cp.async.wait_group 1;" ::: "memory")

__device__ __forceinline__ void ldsm_x4(uint32_t addr, uint32_t* r) {
    asm volatile("ldmatrix.sync.aligned.m8n8.x4.shared.b16 {%0,%1,%2,%3}, [%4];"
                 : "=r"(r[0]), "=r"(r[1]), "=r"(r[2]), "=r"(r[3]) : "r"(addr));
}
__device__ __forceinline__ void ldsm_x4_t(uint32_t addr, uint32_t* r) {
    asm volatile("ldmatrix.sync.aligned.m8n8.x4.trans.shared.b16 {%0,%1,%2,%3}, [%4];"
                 : "=r"(r[0]), "=r"(r[1]), "=r"(r[2]), "=r"(r[3]) : "r"(addr));
}
__device__ __forceinline__ void mma_bf16(float* d, const uint32_t* a,
                                         uint32_t b0, uint32_t b1) {
    asm volatile("mma.sync.aligned.m16n8k16.row.col.f32.bf16.bf16.f32 "
                 "{%0,%1,%2,%3}, {%4,%5,%6,%7}, {%8,%9}, {%0,%1,%2,%3};"
                 : "+f"(d[0]), "+f"(d[1]), "+f"(d[2]), "+f"(d[3])
                 : "r"(a[0]), "r"(a[1]), "r"(a[2]), "r"(a[3]),
                   "r"(b0), "r"(b1));
}
__device__ __forceinline__ void split2(float a, float b, uint32_t& hi, uint32_t& lo) {
    __nv_bfloat16 ha = __float2bfloat16(a), hb = __float2bfloat16(b);
    __nv_bfloat16 la = __float2bfloat16(a - __bfloat162float(ha));
    __nv_bfloat16 lb = __float2bfloat16(b - __bfloat162float(hb));
    hi = ((uint32_t)__bfloat16_as_ushort(hb) << 16) | __bfloat16_as_ushort(ha);
    lo = ((uint32_t)__bfloat16_as_ushort(lb) << 16) | __bfloat16_as_ushort(la);
}

// ---------------------------------------------------------------------------
// fused fp32 -> (hi, lo) bf16 split for all 7 tensors in one launch
// ---------------------------------------------------------------------------
struct SplitArgs {
    const float* src[7];
    __nv_bfloat16* hi[7];
    __nv_bfloat16* lo[7];
};

__global__ void __launch_bounds__(256) split_all_kernel(SplitArgs args)
{
    int b = blockIdx.x;
    int seg, off;
    if (b < 3 * 4096) { seg = b >> 12; off = b & 4095; }
    else { b -= 3 * 4096; seg = 3 + (b >> 10); off = b & 1023; }
    const int i = (off * 256 + threadIdx.x) * 4;
    float4 v = *reinterpret_cast<const float4*>(args.src[seg] + i);
    uint32_t h01, h23, l01, l23;
    split2(v.x, v.y, h01, l01);
    split2(v.z, v.w, h23, l23);
    *reinterpret_cast<uint2*>(args.hi[seg] + i) = make_uint2(h01, h23);
    *reinterpret_cast<uint2*>(args.lo[seg] + i) = make_uint2(l01, l23);
}

// ---------------------------------------------------------------------------
// mma.sync bf16 GEMM, hi/lo split (3 HMMAs / product).
// 512 threads, warp tile 32x32. K-chunk 64 (16 chunks): half the barrier /
// pipeline rounds of the K-chunk-32 version. Row stride 144B, conflict-free.
// ---------------------------------------------------------------------------
constexpr int TILE_B = 128 * 144;     // 18432 per (Ah|Al|Wh|Wl) tile
constexpr int STAGE  = 4 * TILE_B;    // 73728
constexpr int GEMM_SMEM = 2 * STAGE;  // 147456
constexpr int NC = GK / 64;           // 16 chunks

struct GemmBatch {
    const __nv_bfloat16* Ah[3];
    const __nv_bfloat16* Al[3];
    const __nv_bfloat16* Wh[3];
    const __nv_bfloat16* Wl[3];
    const float* bias[3];
    float* C[3];
    __nv_bfloat16* Ch[3];
    __nv_bfloat16* Cl[3];
};

template <int MODE>
__global__ void __launch_bounds__(512, 1) gemm_mma(GemmBatch args)
{
    extern __shared__ __align__(128) uint8_t smem[];
    const uint32_t sbase = smem_u32(smem);
    const int z = blockIdx.z;
    const int tid = threadIdx.x;
    const int lane = tid & 31;
    const int wid = tid >> 5;        // 0..15
    const int warp_m = wid >> 2;     // 0..3
    const int warp_n = wid & 3;      // 0..3
    const int m0 = blockIdx.y * 128;
    const int n0 = blockIdx.x * 128;

    // loader: 4 threads/row, 32B each -> 2 cp16 per tile per thread per chunk
    const int lrow = tid >> 2;       // 0..127
    const int lseg = tid & 3;        // which 32B quarter of the 128B chunk-row
    const __nv_bfloat16* srcs[4] = {
        args.Ah[z] + (size_t)(m0 + lrow) * GK + lseg * 16,
        args.Al[z] + (size_t)(m0 + lrow) * GK + lseg * 16,
        args.Wh[z] + (size_t)(n0 + lrow) * GK + lseg * 16,
        args.Wl[z] + (size_t)(n0 + lrow) * GK + lseg * 16};
    const uint32_t sdst = sbase + lrow * 144 + lseg * 32;

    float acc[2][4][4];
#pragma unroll
    for (int mt = 0; mt < 2; mt++)
#pragma unroll
        for (int nt = 0; nt < 4; nt++)
#pragma unroll
            for (int r = 0; r < 4; r++) acc[mt][nt][r] = 0.f;

    {
#pragma unroll
        for (int t = 0; t < 4; t++) {
            cp16(sdst + t * TILE_B, srcs[t]);
            cp16(sdst + t * TILE_B + 16, srcs[t] + 8);
        }
        CP_COMMIT();
    }

    for (int c = 0; c < NC; c++) {
        if (c + 1 < NC) {
            const uint32_t st = ((c + 1) & 1) * STAGE;
#pragma unroll
            for (int t = 0; t < 4; t++) {
                cp16(sdst + st + t * TILE_B, srcs[t] + (c + 1) * 64);
                cp16(sdst + st + t * TILE_B + 16, srcs[t] + (c + 1) * 64 + 8);
            }
        }
        CP_COMMIT();
        CP_WAIT1();
        __syncthreads();

        const uint32_t st = sbase + (c & 1) * STAGE;
#pragma unroll
        for (int k16 = 0; k16 < 4; k16++) {
            uint32_t ah[2][4], al[2][4], bh[2][4], bl[2][4];
            const uint32_t a_base =
                st + (warp_m * 32 + (lane & 15)) * 144 + ((lane >> 4) * 16) + k16 * 32;
            const int bg = lane >> 3;
            const uint32_t b_base =
                st + 2 * TILE_B +
                (warp_n * 32 + (bg >> 1) * 8 + (lane & 7)) * 144 +
                ((bg & 1) * 16) + k16 * 32;
#pragma unroll
            for (int mt = 0; mt < 2; mt++) {
                ldsm_x4(a_base + mt * 16 * 144, ah[mt]);
                ldsm_x4(a_base + TILE_B + mt * 16 * 144, al[mt]);
            }
#pragma unroll
            for (int ntp = 0; ntp < 2; ntp++) {
                ldsm_x4(b_base + ntp * 16 * 144, bh[ntp]);
                ldsm_x4(b_base + TILE_B + ntp * 16 * 144, bl[ntp]);
            }
#pragma unroll
            for (int mt = 0; mt < 2; mt++)
#pragma unroll
                for (int ntp = 0; ntp < 2; ntp++)
#pragma unroll
                    for (int hf = 0; hf < 2; hf++)
                        mma_bf16(acc[mt][ntp * 2 + hf], ah[mt],
                                 bh[ntp][hf * 2], bh[ntp][hf * 2 + 1]);
#pragma unroll
            for (int mt = 0; mt < 2; mt++)
#pragma unroll
                for (int ntp = 0; ntp < 2; ntp++)
#pragma unroll
                    for (int hf = 0; hf < 2; hf++)
                        mma_bf16(acc[mt][ntp * 2 + hf], ah[mt],
                                 bl[ntp][hf * 2], bl[ntp][hf * 2 + 1]);
#pragma unroll
            for (int mt = 0; mt < 2; mt++)
#pragma unroll
                for (int ntp = 0; ntp < 2; ntp++)
#pragma unroll
                    for (int hf = 0; hf < 2; hf++)
                        mma_bf16(acc[mt][ntp * 2 + hf], al[mt],
                                 bh[ntp][hf * 2], bh[ntp][hf * 2 + 1]);
        }
        __syncthreads();
    }

#pragma unroll
    for (int mt = 0; mt < 2; mt++) {
#pragma unroll
        for (int nt = 0; nt < 4; nt++) {
            const int colg = n0 + warp_n * 32 + nt * 8 + (lane & 3) * 2;
            const float2 bv = *reinterpret_cast<const float2*>(&args.bias[z][colg]);
#pragma unroll
            for (int half = 0; half < 2; half++) {
                const int rowg = m0 + warp_m * 32 + mt * 16 + (lane >> 2) + half * 8;
                const float ox = acc[mt][nt][half * 2 + 0] + bv.x;
                const float oy = acc[mt][nt][half * 2 + 1] + bv.y;
                if (MODE == 1) {
                    const int b = rowg >> 11, s = rowg & 2047;
                    const int h = colg >> 6, d = colg & 63;
                    const size_t idx = (((size_t)b * NHEAD + h) * SEQ + s) * DHEAD + d;
                    uint32_t hi, lo;
                    split2(ox, oy, hi, lo);
                    *reinterpret_cast<uint32_t*>(args.Ch[z] + idx) = hi;
                    *reinterpret_cast<uint32_t*>(args.Cl[z] + idx) = lo;
                } else {
                    float2 o; o.x = ox; o.y = oy;
                    *reinterpret_cast<float2*>(&args.C[z][(size_t)rowg * GN + colg]) = o;
                }
            }
        }
    }
}

// ---------------------------------------------------------------------------
// Tensor-core flash attention (causal), bf16 hi/lo mma.sync.
// NEW: causal n-tile skipping on diagonal kblocks (uniform per-warp branch).
// ---------------------------------------------------------------------------
constexpr int AQ_BYTES  = 128 * 144;
constexpr int AKV_BYTES = 64 * 144;
constexpr int ASTAGE    = 4 * AKV_BYTES;
constexpr int ATT_SMEM  = 2 * AQ_BYTES + 2 * ASTAGE;  // 110592

__global__ void __launch_bounds__(256, 2) attn_mma(
    const __nv_bfloat16* __restrict__ Qh, const __nv_bfloat16* __restrict__ Ql,
    const __nv_bfloat16* __restrict__ Kh, const __nv_bfloat16* __restrict__ Kl,
    const __nv_bfloat16* __restrict__ Vh, const __nv_bfloat16* __restrict__ Vl,
    __nv_bfloat16* __restrict__ Ch, __nv_bfloat16* __restrict__ Cl)
{
    extern __shared__ __align__(128) uint8_t smem[];
    const uint32_t sbase = smem_u32(smem);
    const int tid = threadIdx.x, lane = tid & 31, wm = tid >> 5;
    const int qb = gridDim.x - 1 - blockIdx.x;
    const int bh = blockIdx.y;
    const size_t base = (size_t)bh * SEQ * DHEAD;
    const int nkb = 2 * qb + 2;
    const int wrow_max = qb * 128 + wm * 16 + 15;   // warp's last q row

    {
        const int r = tid >> 1, half = tid & 1;
        const size_t g = base + (size_t)(qb * 128 + r) * DHEAD + half * 32;
        const uint32_t d = sbase + r * 144 + half * 64;
#pragma unroll
        for (int i = 0; i < 4; i++) {
            cp16(d + i * 16, Qh + g + i * 8);
            cp16(d + AQ_BYTES + i * 16, Ql + g + i * 8);
        }
    }
    auto loadKV = [&](int kb) {
        const uint32_t ss = sbase + 2 * AQ_BYTES + (kb & 1) * ASTAGE;
        const int r = tid >> 2, seg = tid & 3;
        const size_t g = base + (size_t)(kb * 64 + r) * DHEAD + seg * 16;
        const uint32_t d = ss + r * 144 + seg * 32;
        cp16(d, Kh + g);                      cp16(d + 16, Kh + g + 8);
        cp16(d + AKV_BYTES, Kl + g);          cp16(d + AKV_BYTES + 16, Kl + g + 8);
        cp16(d + 2 * AKV_BYTES, Vh + g);      cp16(d + 2 * AKV_BYTES + 16, Vh + g + 8);
        cp16(d + 3 * AKV_BYTES, Vl + g);      cp16(d + 3 * AKV_BYTES + 16, Vl + g + 8);
    };
    loadKV(0);
    CP_COMMIT();

    float m0 = -1e30f, m1 = -1e30f, l0 = 0.f, l1 = 0.f;
    float acco[8][4];
#pragma unroll
    for (int nt = 0; nt < 8; nt++)
#pragma unroll
        for (int e = 0; e < 4; e++) acco[nt][e] = 0.f;

    const int bg = lane >> 3;
    const uint32_t aq = sbase + (wm * 16 + (lane & 15)) * 144 + (lane >> 4) * 16;

    for (int kb = 0; kb < nkb; kb++) {
        if (kb + 1 < nkb) loadKV(kb + 1);
        CP_COMMIT();
        CP_WAIT1();
        __syncthreads();
        const uint32_t ss = sbase + 2 * AQ_BYTES + (kb & 1) * ASTAGE;
        const int kcol0 = kb * 64;

        float accs[8][4];
#pragma unroll
        for (int nt = 0; nt < 8; nt++)
#pragma unroll
            for (int e = 0; e < 4; e++) accs[nt][e] = 0.f;

        const uint32_t kbase = ss + ((bg >> 1) * 8 + (lane & 7)) * 144 + (bg & 1) * 16;
#pragma unroll
        for (int kc = 0; kc < 4; kc++) {
            uint32_t qh4[4], ql4[4], kh4[4][4], kl4[4][4];
            ldsm_x4(aq + kc * 32, qh4);
            ldsm_x4(aq + AQ_BYTES + kc * 32, ql4);
#pragma unroll
            for (int ntp = 0; ntp < 4; ntp++) {
                if (kcol0 + ntp * 16 > wrow_max) continue;   // fully masked n-tile
                ldsm_x4(kbase + ntp * 16 * 144 + kc * 32, kh4[ntp]);
                ldsm_x4(kbase + AKV_BYTES + ntp * 16 * 144 + kc * 32, kl4[ntp]);
            }
#pragma unroll
            for (int ntp = 0; ntp < 4; ntp++) {
                if (kcol0 + ntp * 16 > wrow_max) continue;
#pragma unroll
                for (int hf = 0; hf < 2; hf++)
                    mma_bf16(accs[ntp * 2 + hf], qh4,
                             kh4[ntp][hf * 2], kh4[ntp][hf * 2 + 1]);
            }
#pragma unroll
            for (int ntp = 0; ntp < 4; ntp++) {
                if (kcol0 + ntp * 16 > wrow_max) continue;
#pragma unroll
                for (int hf = 0; hf < 2; hf++)
                    mma_bf16(accs[ntp * 2 + hf], qh4,
                             kl4[ntp][hf * 2], kl4[ntp][hf * 2 + 1]);
            }
#pragma unroll
            for (int ntp = 0; ntp < 4; ntp++) {
                if (kcol0 + ntp * 16 > wrow_max) continue;
#pragma unroll
                for (int hf = 0; hf < 2; hf++)
                    mma_bf16(accs[ntp * 2 + hf], ql4,
                             kh4[ntp][hf * 2], kh4[ntp][hf * 2 + 1]);
            }
        }

        const int r0 = qb * 128 + wm * 16 + (lane >> 2);
        const bool needMask = (kcol0 + 63 > qb * 128 + wm * 16);
        float mx0 = -1e30f, mx1 = -1e30f;
#pragma unroll
        for (int nt = 0; nt < 8; nt++) {
#pragma unroll
            for (int e = 0; e < 4; e++) {
                float s = accs[nt][e] * 0.125f;
                if (needMask) {
                    const int col = kcol0 + nt * 8 + (lane & 3) * 2 + (e & 1);
                    const int row = r0 + (e >> 1) * 8;
                    if (col > row) s = -1e30f;
                }
                accs[nt][e] = s;
            }
            mx0 = fmaxf(mx0, fmaxf(accs[nt][0], accs[nt][1]));
            mx1 = fmaxf(mx1, fmaxf(accs[nt][2], accs[nt][3]));
        }
        mx0 = fmaxf(mx0, __shfl_xor_sync(0xffffffffu, mx0, 1));
        mx0 = fmaxf(mx0, __shfl_xor_sync(0xffffffffu, mx0, 2));
        mx1 = fmaxf(mx1, __shfl_xor_sync(0xffffffffu, mx1, 1));
        mx1 = fmaxf(mx1, __shfl_xor_sync(0xffffffffu, mx1, 2));
        const float mn0 = fmaxf(m0, mx0), mn1 = fmaxf(m1, mx1);
        const float al0 = __expf(m0 - mn0), al1 = __expf(m1 - mn1);
        float rs0 = 0.f, rs1 = 0.f;
#pragma unroll
        for (int nt = 0; nt < 8; nt++) {
            accs[nt][0] = __expf(accs[nt][0] - mn0);
            accs[nt][1] = __expf(accs[nt][1] - mn0);
            accs[nt][2] = __expf(accs[nt][2] - mn1);
            accs[nt][3] = __expf(accs[nt][3] - mn1);
            rs0 += accs[nt][0] + accs[nt][1];
            rs1 += accs[nt][2] + accs[nt][3];
        }
        rs0 += __shfl_xor_sync(0xffffffffu, rs0, 1);
        rs0 += __shfl_xor_sync(0xffffffffu, rs0, 2);
        rs1 += __shfl_xor_sync(0xffffffffu, rs1, 1);
        rs1 += __shfl_xor_sync(0xffffffffu, rs1, 2);
        l0 = l0 * al0 + rs0; l1 = l1 * al1 + rs1;
        m0 = mn0; m1 = mn1;
#pragma unroll
        for (int nt = 0; nt < 8; nt++) {
            acco[nt][0] *= al0; acco[nt][1] *= al0;
            acco[nt][2] *= al1; acco[nt][3] *= al1;
        }

#pragma unroll
        for (int c = 0; c < 4; c++) {
            if (kcol0 + c * 16 > wrow_max) continue;   // P tile is all zeros
            uint32_t pah[4], pal[4];
            split2(accs[2 * c][0], accs[2 * c][1], pah[0], pal[0]);
            split2(accs[2 * c][2], accs[2 * c][3], pah[1], pal[1]);
            split2(accs[2 * c + 1][0], accs[2 * c + 1][1], pah[2], pal[2]);
            split2(accs[2 * c + 1][2], accs[2 * c + 1][3], pah[3], pal[3]);
            const uint32_t vb = ss + 2 * AKV_BYTES +
                (c * 16 + (bg & 1) * 8 + (lane & 7)) * 144 + (bg >> 1) * 16;
            uint32_t vh4[4][4], vl4[4][4];
#pragma unroll
            for (int dp = 0; dp < 4; dp++) {
                ldsm_x4_t(vb + dp * 32, vh4[dp]);
                ldsm_x4_t(vb + AKV_BYTES + dp * 32, vl4[dp]);
            }
#pragma unroll
            for (int dp = 0; dp < 4; dp++)
#pragma unroll
                for (int hf = 0; hf < 2; hf++)
                    mma_bf16(acco[dp * 2 + hf], pah,
                             vh4[dp][hf * 2], vh4[dp][hf * 2 + 1]);
#pragma unroll
            for (int dp = 0; dp < 4; dp++)
#pragma unroll
                for (int hf = 0; hf < 2; hf++)
                    mma_bf16(acco[dp * 2 + hf], pah,
                             vl4[dp][hf * 2], vl4[dp][hf * 2 + 1]);
#pragma unroll
            for (int dp = 0; dp < 4; dp++)
#pragma unroll
                for (int hf = 0; hf < 2; hf++)
                    mma_bf16(acco[dp * 2 + hf], pal,
                             vh4[dp][hf * 2], vh4[dp][hf * 2 + 1]);
        }
        __syncthreads();
    }

    const int b = bh >> 4, h = bh & 15;
    const float i0 = 1.f / l0, i1 = 1.f / l1;
    const size_t tok = (size_t)b * SEQ + qb * 128 + wm * 16 + (lane >> 2);
#pragma unroll
    for (int nt = 0; nt < 8; nt++) {
        const int d0 = h * DHEAD + nt * 8 + (lane & 3) * 2;
        uint32_t hi, lo;
        split2(acco[nt][0] * i0, acco[nt][1] * i0, hi, lo);
        *reinterpret_cast<uint32_t*>(Ch + tok * DMODEL + d0) = hi;
        *reinterpret_cast<uint32_t*>(Cl + tok * DMODEL + d0) = lo;
        split2(acco[nt][2] * i1, acco[nt][3] * i1, hi, lo);
        *reinterpret_cast<uint32_t*>(Ch + (tok + 8) * DMODEL + d0) = hi;
        *reinterpret_cast<uint32_t*>(Cl + (tok + 8) * DMODEL + d0) = lo;
    }
}

// ---------------------------------------------------------------------------
extern "C" void kernel_launch(void* const* d_in, const int* in_sizes, int n_in,
                              void* d_out, int out_size)
{
    const float* q   = (const float*)d_in[0];
    const float* k   = (const float*)d_in[1];
    const float* v   = (const float*)d_in[2];
    const float* w_q = (const float*)d_in[4];
    const float* b_q = (const float*)d_in[5];
    const float* w_k = (const float*)d_in[6];
    const float* b_k = (const float*)d_in[7];
    const float* w_v = (const float*)d_in[8];
    const float* b_v = (const float*)d_in[9];
    const float* w_o = (const float*)d_in[10];
    const float* b_o = (const float*)d_in[11];
    float* out = (float*)d_out;

    __nv_bfloat16 *ah, *al, *wh, *wl, *ch, *cl;
    __nv_bfloat16 *qh, *ql, *kh, *kl, *vh, *vl;
    cudaGetSymbolAddress((void**)&ah, g_ah);
    cudaGetSymbolAddress((void**)&al, g_al);
    cudaGetSymbolAddress((void**)&wh, g_wh);
    cudaGetSymbolAddress((void**)&wl, g_wl);
    cudaGetSymbolAddress((void**)&ch, g_ch);
    cudaGetSymbolAddress((void**)&cl, g_cl);
    cudaGetSymbolAddress((void**)&qh, g_qh);
    cudaGetSymbolAddress((void**)&ql, g_ql);
    cudaGetSymbolAddress((void**)&kh, g_kh2);
    cudaGetSymbolAddress((void**)&kl, g_kl2);
    cudaGetSymbolAddress((void**)&vh, g_vh2);
    cudaGetSymbolAddress((void**)&vl, g_vl2);

    static bool attr_set = false;
    if (!attr_set) {
        cudaFuncSetAttribute(gemm_mma<0>,
                             cudaFuncAttributeMaxDynamicSharedMemorySize, GEMM_SMEM);
        cudaFuncSetAttribute(gemm_mma<1>,
                             cudaFuncAttributeMaxDynamicSharedMemorySize, GEMM_SMEM);
        cudaFuncSetAttribute(attn_mma,
                             cudaFuncAttributeMaxDynamicSharedMemorySize, ATT_SMEM);
        attr_set = true;
    }

    const size_t nX = (size_t)GM * GK;
    const size_t nW = (size_t)GN * GK;

    SplitArgs sa;
    sa.src[0] = q;   sa.hi[0] = ah;          sa.lo[0] = al;
    sa.src[1] = k;   sa.hi[1] = ah + nX;     sa.lo[1] = al + nX;
    sa.src[2] = v;   sa.hi[2] = ah + 2 * nX; sa.lo[2] = al + 2 * nX;
    sa.src[3] = w_q; sa.hi[3] = wh;          sa.lo[3] = wl;
    sa.src[4] = w_k; sa.hi[4] = wh + nW;     sa.lo[4] = wl + nW;
    sa.src[5] = w_v; sa.hi[5] = wh + 2 * nW; sa.lo[5] = wl + 2 * nW;
    sa.src[6] = w_o; sa.hi[6] = wh + 3 * nW; sa.lo[6] = wl + 3 * nW;
    split_all_kernel<<<3 * 4096 + 4 * 1024, 256>>>(sa);

    GemmBatch gb;
    gb.Ah[0] = ah;          gb.Al[0] = al;
    gb.Ah[1] = ah + nX;     gb.Al[1] = al + nX;
    gb.Ah[2] = ah + 2 * nX; gb.Al[2] = al + 2 * nX;
    gb.Wh[0] = wh;          gb.Wl[0] = wl;
    gb.Wh[1] = wh + nW;     gb.Wl[1] = wl + nW;
    gb.Wh[2] = wh + 2 * nW; gb.Wl[2] = wl + 2 * nW;
    gb.bias[0] = b_q; gb.bias[1] = b_k; gb.bias[2] = b_v;
    gb.C[0] = gb.C[1] = gb.C[2] = nullptr;
    gb.Ch[0] = qh; gb.Cl[0] = ql;
    gb.Ch[1] = kh; gb.Cl[1] = kl;
    gb.Ch[2] = vh; gb.Cl[2] = vl;
    gemm_mma<1><<<dim3(GN / 128, GM / 128, 3), 512, GEMM_SMEM>>>(gb);

    attn_mma<<<dim3(SEQ / 128, BSZ * NHEAD), 256, ATT_SMEM>>>(
        qh, ql, kh, kl, vh, vl, ch, cl);

    GemmBatch go;
    go.Ah[0] = ch; go.Al[0] = cl;
    go.Wh[0] = wh + 3 * nW; go.Wl[0] = wl + 3 * nW;
    go.bias[0] = b_o;
    go.C[0] = out;
    go.Ch[0] = nullptr; go.Cl[0] = nullptr;
    go.Ah[1] = go.Ah[2] = nullptr; go.Al[1] = go.Al[2] = nullptr;
    go.Wh[1] = go.Wh[2] = nullptr; go.Wl[1] = go.Wl[2] = nullptr;
    go.bias[1] = go.bias[2] = nullptr;
    go.C[1] = go.C[2] = nullptr;
    go.Ch[1] = go.Ch[2] = nullptr; go.Cl[1] = go.Cl[2] = nullptr;
    gemm_mma<0><<<dim3(GN / 128, GM / 128, 1), 512, GEMM_SMEM>>>(go);
}

// round 17
// speedup vs baseline: 1.0883x; 1.0883x over previous
#include <cuda_runtime.h>
#include <cuda_bf16.h>
#include <cstdint>

#define BSZ 2
#define SEQ 2048
#define DMODEL 1024
#define NHEAD 16
#define DHEAD 64

constexpr int GM = BSZ * SEQ;     // 4096
constexpr int GN = DMODEL;        // 1024
constexpr int GK = DMODEL;        // 1024

// ---------------- scratch (allocation-free device globals) ----------------
__device__ __nv_bfloat16 g_ah[3][GM * GK];
__device__ __nv_bfloat16 g_al[3][GM * GK];
__device__ __nv_bfloat16 g_wh[4][GN * GK];
__device__ __nv_bfloat16 g_wl[4][GN * GK];
__device__ __nv_bfloat16 g_qh[BSZ * NHEAD * SEQ * DHEAD];
__device__ __nv_bfloat16 g_ql[BSZ * NHEAD * SEQ * DHEAD];
__device__ __nv_bfloat16 g_kh2[BSZ * NHEAD * SEQ * DHEAD];
__device__ __nv_bfloat16 g_kl2[BSZ * NHEAD * SEQ * DHEAD];
__device__ __nv_bfloat16 g_vh2[BSZ * NHEAD * SEQ * DHEAD];
__device__ __nv_bfloat16 g_vl2[BSZ * NHEAD * SEQ * DHEAD];
__device__ __nv_bfloat16 g_ch[GM * GK];
__device__ __nv_bfloat16 g_cl[GM * GK];

// ---------------------------- PTX helpers ---------------------------------
__device__ __forceinline__ uint32_t smem_u32(const void* p) {
    uint32_t a;
    asm("{ .reg .u64 t; cvta.to.shared.u64 t, %1; cvt.u32.u64 %0, t; }"
        : "=r"(a) : "l"(p));
    return a;
}
__device__ __forceinline__ void cp16(uint32_t dst, const void* src) {
    asm volatile("cp.async.cg.shared.global [%0], [%1], 16;"
                 :: "r"(dst), "l"(src) : "memory");
}
#define CP_COMMIT() asm volatile("cp.async.commit_group;" ::: "memory")
#define CP_WAIT1()  asm volatile("cp.async.wait_group 1;" ::: "memory")

__device__ __forceinline__ void ldsm_x4(uint32_t addr, uint32_t* r) {
    asm volatile("ldmatrix.sync.aligned.m8n8.x4.shared.b16 {%0,%1,%2,%3}, [%4];"
                 : "=r"(r[0]), "=r"(r[1]), "=r"(r[2]), "=r"(r[3]) : "r"(addr));
}
__device__ __forceinline__ void ldsm_x4_t(uint32_t addr, uint32_t* r) {
    asm volatile("ldmatrix.sync.aligned.m8n8.x4.trans.shared.b16 {%0,%1,%2,%3}, [%4];"
                 : "=r"(r[0]), "=r"(r[1]), "=r"(r[2]), "=r"(r[3]) : "r"(addr));
}
__device__ __forceinline__ void mma_bf16(float* d, const uint32_t* a,
                                         uint32_t b0, uint32_t b1) {
    asm volatile("mma.sync.aligned.m16n8k16.row.col.f32.bf16.bf16.f32 "
                 "{%0,%1,%2,%3}, {%4,%5,%6,%7}, {%8,%9}, {%0,%1,%2,%3};"
                 : "+f"(d[0]), "+f"(d[1]), "+f"(d[2]), "+f"(d[3])
                 : "r"(a[0]), "r"(a[1]), "r"(a[2]), "r"(a[3]),
                   "r"(b0), "r"(b1));
}
__device__ __forceinline__ void split2(float a, float b, uint32_t& hi, uint32_t& lo) {
    __nv_bfloat16 ha = __float2bfloat16(a), hb = __float2bfloat16(b);
    __nv_bfloat16 la = __float2bfloat16(a - __bfloat162float(ha));
    __nv_bfloat16 lb = __float2bfloat16(b - __bfloat162float(hb));
    hi = ((uint32_t)__bfloat16_as_ushort(hb) << 16) | __bfloat16_as_ushort(ha);
    lo = ((uint32_t)__bfloat16_as_ushort(lb) << 16) | __bfloat16_as_ushort(la);
}

// ---------------------------------------------------------------------------
// fused fp32 -> (hi, lo) bf16 split for all 7 tensors in one launch
// ---------------------------------------------------------------------------
struct SplitArgs {
    const float* src[7];
    __nv_bfloat16* hi[7];
    __nv_bfloat16* lo[7];
};

__global__ void __launch_bounds__(256) split_all_kernel(SplitArgs args)
{
    int b = blockIdx.x;
    int seg, off;
    if (b < 3 * 4096) { seg = b >> 12; off = b & 4095; }
    else { b -= 3 * 4096; seg = 3 + (b >> 10); off = b & 1023; }
    const int i = (off * 256 + threadIdx.x) * 4;
    float4 v = *reinterpret_cast<const float4*>(args.src[seg] + i);
    uint32_t h01, h23, l01, l23;
    split2(v.x, v.y, h01, l01);
    split2(v.z, v.w, h23, l23);
    *reinterpret_cast<uint2*>(args.hi[seg] + i) = make_uint2(h01, h23);
    *reinterpret_cast<uint2*>(args.lo[seg] + i) = make_uint2(l01, l23);
}

// ---------------------------------------------------------------------------
// mma.sync bf16 GEMM, hi/lo split. Fragments front-loaded per k16;
// 48 MMAs at same-acc reuse distance 16. (Best-measured config, R13.)
// ---------------------------------------------------------------------------
constexpr int TILE_B = 128 * 80;
constexpr int STAGE  = 4 * TILE_B;
constexpr int GEMM_SMEM = 2 * STAGE; // 81920
constexpr int NC = GK / 32;

struct GemmBatch {
    const __nv_bfloat16* Ah[3];
    const __nv_bfloat16* Al[3];
    const __nv_bfloat16* Wh[3];
    const __nv_bfloat16* Wl[3];
    const float* bias[3];
    float* C[3];
    __nv_bfloat16* Ch[3];
    __nv_bfloat16* Cl[3];
};

template <int MODE>
__global__ void __launch_bounds__(256, 2) gemm_mma(GemmBatch args)
{
    extern __shared__ __align__(128) uint8_t smem[];
    const uint32_t sbase = smem_u32(smem);
    const int z = blockIdx.z;
    const int tid = threadIdx.x;
    const int lane = tid & 31;
    const int wid = tid >> 5;
    const int warp_m = wid >> 1;
    const int warp_n = wid & 1;
    const int m0 = blockIdx.y * 128;
    const int n0 = blockIdx.x * 128;

    const int lrow = tid >> 1;
    const int lq = tid & 1;
    const __nv_bfloat16* srcs[4] = {
        args.Ah[z] + (size_t)(m0 + lrow) * GK + lq * 16,
        args.Al[z] + (size_t)(m0 + lrow) * GK + lq * 16,
        args.Wh[z] + (size_t)(n0 + lrow) * GK + lq * 16,
        args.Wl[z] + (size_t)(n0 + lrow) * GK + lq * 16};
    const uint32_t sdst = sbase + lrow * 80 + lq * 32;

    float acc[2][8][4];
#pragma unroll
    for (int mt = 0; mt < 2; mt++)
#pragma unroll
        for (int nt = 0; nt < 8; nt++)
#pragma unroll
            for (int r = 0; r < 4; r++) acc[mt][nt][r] = 0.f;

    {
#pragma unroll
        for (int t = 0; t < 4; t++) {
            cp16(sdst + t * TILE_B, srcs[t]);
            cp16(sdst + t * TILE_B + 16, srcs[t] + 8);
        }
        CP_COMMIT();
    }

    for (int c = 0; c < NC; c++) {
        if (c + 1 < NC) {
            const uint32_t st = ((c + 1) & 1) * STAGE;
#pragma unroll
            for (int t = 0; t < 4; t++) {
                cp16(sdst + st + t * TILE_B, srcs[t] + (c + 1) * 32);
                cp16(sdst + st + t * TILE_B + 16, srcs[t] + (c + 1) * 32 + 8);
            }
        }
        CP_COMMIT();
        CP_WAIT1();
        __syncthreads();

        const uint32_t st = sbase + (c & 1) * STAGE;
#pragma unroll
        for (int k16 = 0; k16 < 2; k16++) {
            // ---- front-load ALL fragments for this k16 ----
            uint32_t ah[2][4], al[2][4], bh[4][4], bl[4][4];
            const uint32_t a_base =
                st + (warp_m * 32 + (lane & 15)) * 80 + ((lane >> 4) * 16) + k16 * 32;
            const int bg = lane >> 3;
            const uint32_t b_base =
                st + 2 * TILE_B +
                (warp_n * 64 + (bg >> 1) * 8 + (lane & 7)) * 80 +
                ((bg & 1) * 16) + k16 * 32;
#pragma unroll
            for (int mt = 0; mt < 2; mt++) {
                ldsm_x4(a_base + mt * 16 * 80, ah[mt]);
                ldsm_x4(a_base + TILE_B + mt * 16 * 80, al[mt]);
            }
#pragma unroll
            for (int ntp = 0; ntp < 4; ntp++) {
                ldsm_x4(b_base + ntp * 16 * 80, bh[ntp]);
                ldsm_x4(b_base + TILE_B + ntp * 16 * 80, bl[ntp]);
            }
            // ---- 48 MMAs, same-acc reuse distance 16 ----
#pragma unroll
            for (int mt = 0; mt < 2; mt++)
#pragma unroll
                for (int ntp = 0; ntp < 4; ntp++)
#pragma unroll
                    for (int hf = 0; hf < 2; hf++)
                        mma_bf16(acc[mt][ntp * 2 + hf], ah[mt],
                                 bh[ntp][hf * 2], bh[ntp][hf * 2 + 1]);
#pragma unroll
            for (int mt = 0; mt < 2; mt++)
#pragma unroll
                for (int ntp = 0; ntp < 4; ntp++)
#pragma unroll
                    for (int hf = 0; hf < 2; hf++)
                        mma_bf16(acc[mt][ntp * 2 + hf], ah[mt],
                                 bl[ntp][hf * 2], bl[ntp][hf * 2 + 1]);
#pragma unroll
            for (int mt = 0; mt < 2; mt++)
#pragma unroll
                for (int ntp = 0; ntp < 4; ntp++)
#pragma unroll
                    for (int hf = 0; hf < 2; hf++)
                        mma_bf16(acc[mt][ntp * 2 + hf], al[mt],
                                 bh[ntp][hf * 2], bh[ntp][hf * 2 + 1]);
        }
        __syncthreads();
    }

#pragma unroll
    for (int mt = 0; mt < 2; mt++) {
#pragma unroll
        for (int nt = 0; nt < 8; nt++) {
            const int colg = n0 + warp_n * 64 + nt * 8 + (lane & 3) * 2;
            const float2 bv = *reinterpret_cast<const float2*>(&args.bias[z][colg]);
#pragma unroll
            for (int half = 0; half < 2; half++) {
                const int rowg = m0 + warp_m * 32 + mt * 16 + (lane >> 2) + half * 8;
                const float ox = acc[mt][nt][half * 2 + 0] + bv.x;
                const float oy = acc[mt][nt][half * 2 + 1] + bv.y;
                if (MODE == 1) {
                    const int b = rowg >> 11, s = rowg & 2047;
                    const int h = colg >> 6, d = colg & 63;
                    const size_t idx = (((size_t)b * NHEAD + h) * SEQ + s) * DHEAD + d;
                    uint32_t hi, lo;
                    split2(ox, oy, hi, lo);
                    *reinterpret_cast<uint32_t*>(args.Ch[z] + idx) = hi;
                    *reinterpret_cast<uint32_t*>(args.Cl[z] + idx) = lo;
                } else {
                    float2 o; o.x = ox; o.y = oy;
                    *reinterpret_cast<float2*>(&args.C[z][(size_t)rowg * GN + colg]) = o;
                }
            }
        }
    }
}

// ---------------------------------------------------------------------------
// Tensor-core flash attention (causal), bf16 hi/lo, front-loaded fragments.
// (Best-measured config, R13.)
// ---------------------------------------------------------------------------
constexpr int AQ_BYTES  = 128 * 144;
constexpr int AKV_BYTES = 64 * 144;
constexpr int ASTAGE    = 4 * AKV_BYTES;
constexpr int ATT_SMEM  = 2 * AQ_BYTES + 2 * ASTAGE;  // 110592

__global__ void __launch_bounds__(256, 2) attn_mma(
    const __nv_bfloat16* __restrict__ Qh, const __nv_bfloat16* __restrict__ Ql,
    const __nv_bfloat16* __restrict__ Kh, const __nv_bfloat16* __restrict__ Kl,
    const __nv_bfloat16* __restrict__ Vh, const __nv_bfloat16* __restrict__ Vl,
    __nv_bfloat16* __restrict__ Ch, __nv_bfloat16* __restrict__ Cl)
{
    extern __shared__ __align__(128) uint8_t smem[];
    const uint32_t sbase = smem_u32(smem);
    const int tid = threadIdx.x, lane = tid & 31, wm = tid >> 5;
    const int qb = gridDim.x - 1 - blockIdx.x;
    const int bh = blockIdx.y;
    const size_t base = (size_t)bh * SEQ * DHEAD;
    const int nkb = 2 * qb + 2;

    {
        const int r = tid >> 1, half = tid & 1;
        const size_t g = base + (size_t)(qb * 128 + r) * DHEAD + half * 32;
        const uint32_t d = sbase + r * 144 + half * 64;
#pragma unroll
        for (int i = 0; i < 4; i++) {
            cp16(d + i * 16, Qh + g + i * 8);
            cp16(d + AQ_BYTES + i * 16, Ql + g + i * 8);
        }
    }
    auto loadKV = [&](int kb) {
        const uint32_t ss = sbase + 2 * AQ_BYTES + (kb & 1) * ASTAGE;
        const int r = tid >> 2, seg = tid & 3;
        const size_t g = base + (size_t)(kb * 64 + r) * DHEAD + seg * 16;
        const uint32_t d = ss + r * 144 + seg * 32;
        cp16(d, Kh + g);                      cp16(d + 16, Kh + g + 8);
        cp16(d + AKV_BYTES, Kl + g);          cp16(d + AKV_BYTES + 16, Kl + g + 8);
        cp16(d + 2 * AKV_BYTES, Vh + g);      cp16(d + 2 * AKV_BYTES + 16, Vh + g + 8);
        cp16(d + 3 * AKV_BYTES, Vl + g);      cp16(d + 3 * AKV_BYTES + 16, Vl + g + 8);
    };
    loadKV(0);
    CP_COMMIT();

    float m0 = -1e30f, m1 = -1e30f, l0 = 0.f, l1 = 0.f;
    float acco[8][4];
#pragma unroll
    for (int nt = 0; nt < 8; nt++)
#pragma unroll
        for (int e = 0; e < 4; e++) acco[nt][e] = 0.f;

    const int bg = lane >> 3;
    const uint32_t aq = sbase + (wm * 16 + (lane & 15)) * 144 + (lane >> 4) * 16;

    for (int kb = 0; kb < nkb; kb++) {
        if (kb + 1 < nkb) loadKV(kb + 1);
        CP_COMMIT();
        CP_WAIT1();
        __syncthreads();
        const uint32_t ss = sbase + 2 * AQ_BYTES + (kb & 1) * ASTAGE;

        // ---- S = Q K^T: per kc front-load 10 ldsm, 24 MMAs distance 8 ----
        float accs[8][4];
#pragma unroll
        for (int nt = 0; nt < 8; nt++)
#pragma unroll
            for (int e = 0; e < 4; e++) accs[nt][e] = 0.f;

        const uint32_t kbase = ss + ((bg >> 1) * 8 + (lane & 7)) * 144 + (bg & 1) * 16;
#pragma unroll
        for (int kc = 0; kc < 4; kc++) {
            uint32_t qh4[4], ql4[4], kh4[4][4], kl4[4][4];
            ldsm_x4(aq + kc * 32, qh4);
            ldsm_x4(aq + AQ_BYTES + kc * 32, ql4);
#pragma unroll
            for (int ntp = 0; ntp < 4; ntp++) {
                ldsm_x4(kbase + ntp * 16 * 144 + kc * 32, kh4[ntp]);
                ldsm_x4(kbase + AKV_BYTES + ntp * 16 * 144 + kc * 32, kl4[ntp]);
            }
#pragma unroll
            for (int ntp = 0; ntp < 4; ntp++)
#pragma unroll
                for (int hf = 0; hf < 2; hf++)
                    mma_bf16(accs[ntp * 2 + hf], qh4,
                             kh4[ntp][hf * 2], kh4[ntp][hf * 2 + 1]);
#pragma unroll
            for (int ntp = 0; ntp < 4; ntp++)
#pragma unroll
                for (int hf = 0; hf < 2; hf++)
                    mma_bf16(accs[ntp * 2 + hf], qh4,
                             kl4[ntp][hf * 2], kl4[ntp][hf * 2 + 1]);
#pragma unroll
            for (int ntp = 0; ntp < 4; ntp++)
#pragma unroll
                for (int hf = 0; hf < 2; hf++)
                    mma_bf16(accs[ntp * 2 + hf], ql4,
                             kh4[ntp][hf * 2], kh4[ntp][hf * 2 + 1]);
        }

        // ---- online softmax ----
        const int r0 = qb * 128 + wm * 16 + (lane >> 2);
        const bool needMask = (kb * 64 + 63 > qb * 128 + wm * 16);
        float mx0 = -1e30f, mx1 = -1e30f;
#pragma unroll
        for (int nt = 0; nt < 8; nt++) {
#pragma unroll
            for (int e = 0; e < 4; e++) {
                float s = accs[nt][e] * 0.125f;
                if (needMask) {
                    const int col = kb * 64 + nt * 8 + (lane & 3) * 2 + (e & 1);
                    const int row = r0 + (e >> 1) * 8;
                    if (col > row) s = -1e30f;
                }
                accs[nt][e] = s;
            }
            mx0 = fmaxf(mx0, fmaxf(accs[nt][0], accs[nt][1]));
            mx1 = fmaxf(mx1, fmaxf(accs[nt][2], accs[nt][3]));
        }
        mx0 = fmaxf(mx0, __shfl_xor_sync(0xffffffffu, mx0, 1));
        mx0 = fmaxf(mx0, __shfl_xor_sync(0xffffffffu, mx0, 2));
        mx1 = fmaxf(mx1, __shfl_xor_sync(0xffffffffu, mx1, 1));
        mx1 = fmaxf(mx1, __shfl_xor_sync(0xffffffffu, mx1, 2));
        const float mn0 = fmaxf(m0, mx0), mn1 = fmaxf(m1, mx1);
        const float al0 = __expf(m0 - mn0), al1 = __expf(m1 - mn1);
        float rs0 = 0.f, rs1 = 0.f;
#pragma unroll
        for (int nt = 0; nt < 8; nt++) {
            accs[nt][0] = __expf(accs[nt][0] - mn0);
            accs[nt][1] = __expf(accs[nt][1] - mn0);
            accs[nt][2] = __expf(accs[nt][2] - mn1);
            accs[nt][3] = __expf(accs[nt][3] - mn1);
            rs0 += accs[nt][0] + accs[nt][1];
            rs1 += accs[nt][2] + accs[nt][3];
        }
        rs0 += __shfl_xor_sync(0xffffffffu, rs0, 1);
        rs0 += __shfl_xor_sync(0xffffffffu, rs0, 2);
        rs1 += __shfl_xor_sync(0xffffffffu, rs1, 1);
        rs1 += __shfl_xor_sync(0xffffffffu, rs1, 2);
        l0 = l0 * al0 + rs0; l1 = l1 * al1 + rs1;
        m0 = mn0; m1 = mn1;
#pragma unroll
        for (int nt = 0; nt < 8; nt++) {
            acco[nt][0] *= al0; acco[nt][1] *= al0;
            acco[nt][2] *= al1; acco[nt][3] *= al1;
        }

        // ---- O += P V: per c front-load 8 V-ldsm, 24 MMAs distance 8 ----
#pragma unroll
        for (int c = 0; c < 4; c++) {
            uint32_t pah[4], pal[4];
            split2(accs[2 * c][0], accs[2 * c][1], pah[0], pal[0]);
            split2(accs[2 * c][2], accs[2 * c][3], pah[1], pal[1]);
            split2(accs[2 * c + 1][0], accs[2 * c + 1][1], pah[2], pal[2]);
            split2(accs[2 * c + 1][2], accs[2 * c + 1][3], pah[3], pal[3]);
            const uint32_t vb = ss + 2 * AKV_BYTES +
                (c * 16 + (bg & 1) * 8 + (lane & 7)) * 144 + (bg >> 1) * 16;
            uint32_t vh4[4][4], vl4[4][4];
#pragma unroll
            for (int dp = 0; dp < 4; dp++) {
                ldsm_x4_t(vb + dp * 32, vh4[dp]);
                ldsm_x4_t(vb + AKV_BYTES + dp * 32, vl4[dp]);
            }
#pragma unroll
            for (int dp = 0; dp < 4; dp++)
#pragma unroll
                for (int hf = 0; hf < 2; hf++)
                    mma_bf16(acco[dp * 2 + hf], pah,
                             vh4[dp][hf * 2], vh4[dp][hf * 2 + 1]);
#pragma unroll
            for (int dp = 0; dp < 4; dp++)
#pragma unroll
                for (int hf = 0; hf < 2; hf++)
                    mma_bf16(acco[dp * 2 + hf], pah,
                             vl4[dp][hf * 2], vl4[dp][hf * 2 + 1]);
#pragma unroll
            for (int dp = 0; dp < 4; dp++)
#pragma unroll
                for (int hf = 0; hf < 2; hf++)
                    mma_bf16(acco[dp * 2 + hf], pal,
                             vh4[dp][hf * 2], vh4[dp][hf * 2 + 1]);
        }
        __syncthreads();
    }

    // ---- epilogue ----
    const int b = bh >> 4, h = bh & 15;
    const float i0 = 1.f / l0, i1 = 1.f / l1;
    const size_t tok = (size_t)b * SEQ + qb * 128 + wm * 16 + (lane >> 2);
#pragma unroll
    for (int nt = 0; nt < 8; nt++) {
        const int d0 = h * DHEAD + nt * 8 + (lane & 3) * 2;
        uint32_t hi, lo;
        split2(acco[nt][0] * i0, acco[nt][1] * i0, hi, lo);
        *reinterpret_cast<uint32_t*>(Ch + tok * DMODEL + d0) = hi;
        *reinterpret_cast<uint32_t*>(Cl + tok * DMODEL + d0) = lo;
        split2(acco[nt][2] * i1, acco[nt][3] * i1, hi, lo);
        *reinterpret_cast<uint32_t*>(Ch + (tok + 8) * DMODEL + d0) = hi;
        *reinterpret_cast<uint32_t*>(Cl + (tok + 8) * DMODEL + d0) = lo;
    }
}

// ---------------------------------------------------------------------------
extern "C" void kernel_launch(void* const* d_in, const int* in_sizes, int n_in,
                              void* d_out, int out_size)
{
    const float* q   = (const float*)d_in[0];
    const float* k   = (const float*)d_in[1];
    const float* v   = (const float*)d_in[2];
    const float* w_q = (const float*)d_in[4];
    const float* b_q = (const float*)d_in[5];
    const float* w_k = (const float*)d_in[6];
    const float* b_k = (const float*)d_in[7];
    const float* w_v = (const float*)d_in[8];
    const float* b_v = (const float*)d_in[9];
    const float* w_o = (const float*)d_in[10];
    const float* b_o = (const float*)d_in[11];
    float* out = (float*)d_out;

    __nv_bfloat16 *ah, *al, *wh, *wl, *ch, *cl;
    __nv_bfloat16 *qh, *ql, *kh, *kl, *vh, *vl;
    cudaGetSymbolAddress((void**)&ah, g_ah);
    cudaGetSymbolAddress((void**)&al, g_al);
    cudaGetSymbolAddress((void**)&wh, g_wh);
    cudaGetSymbolAddress((void**)&wl, g_wl);
    cudaGetSymbolAddress((void**)&ch, g_ch);
    cudaGetSymbolAddress((void**)&cl, g_cl);
    cudaGetSymbolAddress((void**)&qh, g_qh);
    cudaGetSymbolAddress((void**)&ql, g_ql);
    cudaGetSymbolAddress((void**)&kh, g_kh2);
    cudaGetSymbolAddress((void**)&kl, g_kl2);
    cudaGetSymbolAddress((void**)&vh, g_vh2);
    cudaGetSymbolAddress((void**)&vl, g_vl2);

    static bool attr_set = false;
    if (!attr_set) {
        cudaFuncSetAttribute(gemm_mma<0>,
                             cudaFuncAttributeMaxDynamicSharedMemorySize, GEMM_SMEM);
        cudaFuncSetAttribute(gemm_mma<1>,
                             cudaFuncAttributeMaxDynamicSharedMemorySize, GEMM_SMEM);
        cudaFuncSetAttribute(attn_mma,
                             cudaFuncAttributeMaxDynamicSharedMemorySize, ATT_SMEM);
        attr_set = true;
    }

    const size_t nX = (size_t)GM * GK;
    const size_t nW = (size_t)GN * GK;

    SplitArgs sa;
    sa.src[0] = q;   sa.hi[0] = ah;          sa.lo[0] = al;
    sa.src[1] = k;   sa.hi[1] = ah + nX;     sa.lo[1] = al + nX;
    sa.src[2] = v;   sa.hi[2] = ah + 2 * nX; sa.lo[2] = al + 2 * nX;
    sa.src[3] = w_q; sa.hi[3] = wh;          sa.lo[3] = wl;
    sa.src[4] = w_k; sa.hi[4] = wh + nW;     sa.lo[4] = wl + nW;
    sa.src[5] = w_v; sa.hi[5] = wh + 2 * nW; sa.lo[5] = wl + 2 * nW;
    sa.src[6] = w_o; sa.hi[6] = wh + 3 * nW; sa.lo[6] = wl + 3 * nW;
    split_all_kernel<<<3 * 4096 + 4 * 1024, 256>>>(sa);

    GemmBatch gb;
    gb.Ah[0] = ah;          gb.Al[0] = al;
    gb.Ah[1] = ah + nX;     gb.Al[1] = al + nX;
    gb.Ah[2] = ah + 2 * nX; gb.Al[2] = al + 2 * nX;
    gb.Wh[0] = wh;          gb.Wl[0] = wl;
    gb.Wh[1] = wh + nW;     gb.Wl[1] = wl + nW;
    gb.Wh[2] = wh + 2 * nW; gb.Wl[2] = wl + 2 * nW;
    gb.bias[0] = b_q; gb.bias[1] = b_k; gb.bias[2] = b_v;
    gb.C[0] = gb.C[1] = gb.C[2] = nullptr;
    gb.Ch[0] = qh; gb.Cl[0] = ql;
    gb.Ch[1] = kh; gb.Cl[1] = kl;
    gb.Ch[2] = vh; gb.Cl[2] = vl;
    gemm_mma<1><<<dim3(GN / 128, GM / 128, 3), 256, GEMM_SMEM>>>(gb);

    attn_mma<<<dim3(SEQ / 128, BSZ * NHEAD), 256, ATT_SMEM>>>(
        qh, ql, kh, kl, vh, vl, ch, cl);

    GemmBatch go;
    go.Ah[0] = ch; go.Al[0] = cl;
    go.Wh[0] = wh + 3 * nW; go.Wl[0] = wl + 3 * nW;
    go.bias[0] = b_o;
    go.C[0] = out;
    go.Ch[0] = nullptr; go.Cl[0] = nullptr;
    go.Ah[1] = go.Ah[2] = nullptr; go.Al[1] = go.Al[2] = nullptr;
    go.Wh[1] = go.Wh[2] = nullptr; go.Wl[1] = go.Wl[2] = nullptr;
    go.bias[1] = go.bias[2] = nullptr;
    go.C[1] = go.C[2] = nullptr;
    go.Ch[1] = go.Ch[2] = nullptr; go.Cl[1] = go.Cl[2] = nullptr;
    gemm_mma<0><<<dim3(GN / 128, GM / 128, 1), 256, GEMM_SMEM>>>(go);
}